// round 14
// baseline (speedup 1.0000x reference)
#include <cuda_runtime.h>
#include <cstdint>

#define CO 256
#define CI 256
#define NW 12
#define RPW 4   // rows per warp

// (weight pointer, coef) per combo — filled by setup_kernel each launch
__device__ ulonglong2 g_combo[NW];

// Per-lane tap table. Lane L owns acc positions L (acc0) and L+32 (acc1).
// Entry = combo c | tap j << 4 | kernel_size k << 8. Row[0] = cnt | cnt0<<8
// (first cnt0 entries feed acc0, remaining cnt-cnt0 feed acc1).
#define E(c,j) (unsigned short)((c) | ((j)<<4) | ((3 + 2*((c)/3))<<8))
#define H(cnt,cnt0) (unsigned short)((cnt) | ((cnt0)<<8))

__device__ __align__(16) const unsigned short g_tbl[32][16] = {
 {H(2,1),  E(11,0),E(9,8)},
 {H(0,0)},
 {H(3,0),  E(4,4),E(7,5),E(10,6)},
 {H(4,0),  E(2,2),E(5,3),E(8,4),E(11,5)},
 {H(0,0)},
 {H(2,0),  E(7,6),E(10,7)},
 {H(0,0)},
 {H(2,2),  E(8,0),E(11,1)},
 {H(1,0),  E(10,8)},
 {H(0,0)},
 {H(3,0),  E(5,4),E(8,5),E(11,6)},
 {H(0,0)},
 {H(0,0)},
 {H(0,0)},
 {H(3,3),  E(5,0),E(8,1),E(11,2)},
 {H(0,0)},
 {H(1,1),  E(10,0)},
 {H(2,0),  E(8,6),E(11,7)},
 {H(0,0)},
 {H(2,2),  E(7,0),E(10,1)},
 {H(0,0)},
 {H(4,4),  E(2,0),E(5,1),E(8,2),E(11,3)},
 {H(3,3),  E(4,0),E(7,1),E(10,2)},
 {H(0,0)},
 {H(2,1),  E(9,0),E(11,8)},
 {H(6,6),  E(1,0),E(4,1),E(6,0),E(7,2),E(9,1),E(10,3)},
 {H(3,3),  E(3,0),E(6,1),E(9,2)},
 {H(4,4),  E(0,0),E(3,1),E(6,2),E(9,3)},
 {H(12,12),E(0,1),E(1,1),E(2,1),E(3,2),E(4,2),E(5,2),E(6,3),E(7,3),E(8,3),E(9,4),E(10,4),E(11,4)},
 {H(4,4),  E(0,2),E(3,3),E(6,4),E(9,5)},
 {H(3,3),  E(3,4),E(6,5),E(9,6)},
 {H(6,6),  E(1,2),E(4,3),E(6,6),E(7,4),E(9,7),E(10,5)},
};

// softmax(log_softmax(alpha)+gumbels) == softmax(alpha+gumbels); also packs
// (weight ptr, coef) into g_combo for the main kernel.
__global__ void setup_kernel(
    const float* __restrict__ alpha, const float* __restrict__ gumbels,
    const float* w0, const float* w1, const float* w2,  const float* w3,
    const float* w4, const float* w5, const float* w6,  const float* w7,
    const float* w8, const float* w9, const float* w10, const float* w11)
{
    int t = threadIdx.x;  // one warp
    float v = (t < NW) ? (alpha[t] + gumbels[t]) : -1e30f;
    float m = v;
    #pragma unroll
    for (int o = 16; o > 0; o >>= 1) m = fmaxf(m, __shfl_xor_sync(0xffffffffu, m, o));
    float e = (t < NW) ? __expf(v - m) : 0.0f;
    float s = e;
    #pragma unroll
    for (int o = 16; o > 0; o >>= 1) s += __shfl_xor_sync(0xffffffffu, s, o);
    if (t < NW) {
        const float* wtab[NW] = {w0,w1,w2,w3,w4,w5,w6,w7,w8,w9,w10,w11};
        g_combo[t] = make_ulonglong2((unsigned long long)(uintptr_t)wtab[t],
                                     (unsigned long long)__float_as_uint(e / s));
    }
}

// Each WARP handles RPW=4 consecutive rows. Interior zero stores issued first;
// 4 independent register-gather chains (j-outer, row-inner => combo loaded
// once per j); edges gathered via full-mask shuffles. No smem, no barriers.
// Stores use DEFAULT (write-back, evict-normal) policy: across graph replays
// ~126MB of the 268MB output stays resident-dirty in L2, so those stores are
// L2 write hits with no DRAM transaction.
__global__ void __launch_bounds__(256) mcp_kernel(float* __restrict__ out, int N)
{
    const int lane = threadIdx.x & 31;
    const int wip  = threadIdx.x >> 5;
    const int wg   = blockIdx.x * 8 + wip;       // global warp id
    const int row0 = wg * RPW;

    const float4 z = make_float4(0.f, 0.f, 0.f, 0.f);
    const int nIt = N >> 7;                      // 128-float tiles per row

    float4* o[RPW];
    #pragma unroll
    for (int r = 0; r < RPW; ++r)
        o[r] = reinterpret_cast<float4*>(out + (size_t)(row0 + r) * N);

    // 1) Interior zeros first — dominant store stream, no dependencies.
    #pragma unroll
    for (int r = 0; r < RPW; ++r)
        #pragma unroll 6
        for (int it = 1; it < nIt - 1; ++it)
            o[r][it * 32 + lane] = z;

    // 2) Per-lane tap table (L1-resident after first waves).
    const uint4* tp = reinterpret_cast<const uint4*>(&g_tbl[lane][0]);
    uint4 tlo = __ldg(tp);
    uint4 thi = __ldg(tp + 1);
    unsigned words[8] = {tlo.x, tlo.y, tlo.z, tlo.w, thi.x, thi.y, thi.z, thi.w};
    #define UENT(i) ((words[(i) >> 1] >> (((i) & 1) * 16)) & 0xFFFFu)

    const unsigned hdr = UENT(0);
    const int cnt  = hdr & 0xFF;
    const int cnt0 = (int)(hdr >> 8);

    // 3) Gather/accumulate: j outer (combo load once), rows inner (4x MLP).
    float acc0[RPW], acc1[RPW];
    #pragma unroll
    for (int r = 0; r < RPW; ++r) { acc0[r] = 0.f; acc1[r] = 0.f; }

    #pragma unroll
    for (int j = 0; j < 12; ++j) {
        const unsigned ent = UENT(j + 1);
        const int c   = ent & 15;
        const int tap = (ent >> 4) & 15;
        const int k   = (ent >> 8) & 15;
        ulonglong2 cb = __ldg(&g_combo[c]);
        const float* wp = (const float*)(uintptr_t)cb.x;
        const float  cf = __uint_as_float((unsigned)cb.y);
        const bool act  = j < cnt;
        const bool lo   = j < cnt0;
        #pragma unroll
        for (int r = 0; r < RPW; ++r) {
            float wv = act ? __ldg(wp + (size_t)(row0 + r) * k + tap) : 0.f;
            float val = cf * wv;
            if (lo) acc0[r] += val; else acc1[r] += val;
        }
    }
    #undef UENT

    // 4) Edge tiles. pad -> flip -> roll((S+1)//2):
    //    out[t] = acc[28 - t]      t in [0, 29)
    //    out[t] = acc[N + 28 - t]  t in [N-28, N)
    //    Lane L holds acc[L] (acc0) and acc[L+32] (acc1).
    #pragma unroll
    for (int r = 0; r < RPW; ++r) {
        // Head tile: floats [0, 128)
        {
            const int t0 = lane * 4;
            float a[4];
            #pragma unroll
            for (int q = 0; q < 4; ++q) {
                const int idx = 28 - (t0 + q);
                const float g = __shfl_sync(0xffffffffu, acc0[r], idx & 31);
                a[q] = (idx >= 0) ? g : 0.f;
            }
            o[r][lane] = make_float4(a[0], a[1], a[2], a[3]);
        }
        // Tail tile: floats [N-128, N); idx = N+28-t = 156 - 4*lane - q
        {
            float a[4];
            #pragma unroll
            for (int q = 0; q < 4; ++q) {
                const int idx = 156 - lane * 4 - q;   // >= 29 always
                const float glo = __shfl_sync(0xffffffffu, acc0[r], idx & 31);
                const float ghi = __shfl_sync(0xffffffffu, acc1[r], (idx - 32) & 31);
                const float g = (idx < 32) ? glo : ghi;
                a[q] = (idx <= 56) ? g : 0.f;
            }
            o[r][(nIt - 1) * 32 + lane] = make_float4(a[0], a[1], a[2], a[3]);
        }
    }
}

extern "C" void kernel_launch(void* const* d_in, const int* in_sizes, int n_in,
                              void* d_out, int out_size) {
    const float* w[12];
    for (int i = 0; i < 12; ++i) w[i] = (const float*)d_in[i];
    const float* alpha   = (const float*)d_in[12];
    const float* gumbels = (const float*)d_in[13];
    float* out = (float*)d_out;

    const int rows = CO * CI;                 // 65536
    const int N = out_size / rows;            // input_size (1024)

    setup_kernel<<<1, 32>>>(alpha, gumbels,
                            w[0], w[1], w[2], w[3], w[4], w[5],
                            w[6], w[7], w[8], w[9], w[10], w[11]);
    mcp_kernel<<<rows / (8 * RPW), 256>>>(out, N);
}

// round 16
// speedup vs baseline: 1.1562x; 1.1562x over previous
#include <cuda_runtime.h>
#include <cstdint>

#define CO 256
#define CI 256
#define NW 12
#define RPW 2   // rows per warp

// (weight pointer, coef) per combo — filled by setup_kernel each launch
__device__ ulonglong2 g_combo[NW];

// Per-lane tap table. Lane L owns acc positions L (acc0) and L+32 (acc1).
// Entry = combo c | tap j << 4 | kernel_size k << 8. Row[0] = cnt | cnt0<<8
// (first cnt0 entries feed acc0, remaining cnt-cnt0 feed acc1).
#define E(c,j) (unsigned short)((c) | ((j)<<4) | ((3 + 2*((c)/3))<<8))
#define H(cnt,cnt0) (unsigned short)((cnt) | ((cnt0)<<8))

__device__ __align__(16) const unsigned short g_tbl[32][16] = {
 {H(2,1),  E(11,0),E(9,8)},
 {H(0,0)},
 {H(3,0),  E(4,4),E(7,5),E(10,6)},
 {H(4,0),  E(2,2),E(5,3),E(8,4),E(11,5)},
 {H(0,0)},
 {H(2,0),  E(7,6),E(10,7)},
 {H(0,0)},
 {H(2,2),  E(8,0),E(11,1)},
 {H(1,0),  E(10,8)},
 {H(0,0)},
 {H(3,0),  E(5,4),E(8,5),E(11,6)},
 {H(0,0)},
 {H(0,0)},
 {H(0,0)},
 {H(3,3),  E(5,0),E(8,1),E(11,2)},
 {H(0,0)},
 {H(1,1),  E(10,0)},
 {H(2,0),  E(8,6),E(11,7)},
 {H(0,0)},
 {H(2,2),  E(7,0),E(10,1)},
 {H(0,0)},
 {H(4,4),  E(2,0),E(5,1),E(8,2),E(11,3)},
 {H(3,3),  E(4,0),E(7,1),E(10,2)},
 {H(0,0)},
 {H(2,1),  E(9,0),E(11,8)},
 {H(6,6),  E(1,0),E(4,1),E(6,0),E(7,2),E(9,1),E(10,3)},
 {H(3,3),  E(3,0),E(6,1),E(9,2)},
 {H(4,4),  E(0,0),E(3,1),E(6,2),E(9,3)},
 {H(12,12),E(0,1),E(1,1),E(2,1),E(3,2),E(4,2),E(5,2),E(6,3),E(7,3),E(8,3),E(9,4),E(10,4),E(11,4)},
 {H(4,4),  E(0,2),E(3,3),E(6,4),E(9,5)},
 {H(3,3),  E(3,4),E(6,5),E(9,6)},
 {H(6,6),  E(1,2),E(4,3),E(6,6),E(7,4),E(9,7),E(10,5)},
};

// softmax(log_softmax(alpha)+gumbels) == softmax(alpha+gumbels); also packs
// (weight ptr, coef) into g_combo for the main kernel.
__global__ void setup_kernel(
    const float* __restrict__ alpha, const float* __restrict__ gumbels,
    const float* w0, const float* w1, const float* w2,  const float* w3,
    const float* w4, const float* w5, const float* w6,  const float* w7,
    const float* w8, const float* w9, const float* w10, const float* w11)
{
    int t = threadIdx.x;  // one warp
    float v = (t < NW) ? (alpha[t] + gumbels[t]) : -1e30f;
    float m = v;
    #pragma unroll
    for (int o = 16; o > 0; o >>= 1) m = fmaxf(m, __shfl_xor_sync(0xffffffffu, m, o));
    float e = (t < NW) ? __expf(v - m) : 0.0f;
    float s = e;
    #pragma unroll
    for (int o = 16; o > 0; o >>= 1) s += __shfl_xor_sync(0xffffffffu, s, o);
    if (t < NW) {
        const float* wtab[NW] = {w0,w1,w2,w3,w4,w5,w6,w7,w8,w9,w10,w11};
        g_combo[t] = make_ulonglong2((unsigned long long)(uintptr_t)wtab[t],
                                     (unsigned long long)__float_as_uint(e / s));
    }
}

// Each WARP handles RPW=2 consecutive rows — high occupancy (store-drain-
// limited kernel wants many store-eligible warps) with table-decode cost
// amortized 2x vs RPW=1. Zero stores issued first; register gather (j-outer,
// row-inner); edges via full-mask shuffles. No smem, no barriers.
__global__ void __launch_bounds__(256, 6) mcp_kernel(float* __restrict__ out, int N)
{
    const int lane = threadIdx.x & 31;
    const int wip  = threadIdx.x >> 5;
    const int wg   = blockIdx.x * 8 + wip;       // global warp id
    const int row0 = wg * RPW;

    const float4 z = make_float4(0.f, 0.f, 0.f, 0.f);
    const int nIt = N >> 7;                      // 128-float tiles per row

    float4* o[RPW];
    #pragma unroll
    for (int r = 0; r < RPW; ++r)
        o[r] = reinterpret_cast<float4*>(out + (size_t)(row0 + r) * N);

    // 1) Interior zeros first — dominant DRAM stream, no dependencies.
    #pragma unroll
    for (int r = 0; r < RPW; ++r)
        #pragma unroll 6
        for (int it = 1; it < nIt - 1; ++it)
            __stcs(&o[r][it * 32 + lane], z);

    // 2) Per-lane tap table (L1-resident after first waves).
    const uint4* tp = reinterpret_cast<const uint4*>(&g_tbl[lane][0]);
    uint4 tlo = __ldg(tp);
    uint4 thi = __ldg(tp + 1);
    unsigned words[8] = {tlo.x, tlo.y, tlo.z, tlo.w, thi.x, thi.y, thi.z, thi.w};
    #define UENT(i) ((words[(i) >> 1] >> (((i) & 1) * 16)) & 0xFFFFu)

    const unsigned hdr = UENT(0);
    const int cnt  = hdr & 0xFF;
    const int cnt0 = (int)(hdr >> 8);

    // 3) Gather/accumulate: j outer (combo load once), rows inner (2x MLP).
    float acc0[RPW], acc1[RPW];
    #pragma unroll
    for (int r = 0; r < RPW; ++r) { acc0[r] = 0.f; acc1[r] = 0.f; }

    #pragma unroll
    for (int j = 0; j < 12; ++j) {
        const unsigned ent = UENT(j + 1);
        const int c   = ent & 15;
        const int tap = (ent >> 4) & 15;
        const int k   = (ent >> 8) & 15;
        ulonglong2 cb = __ldg(&g_combo[c]);
        const float* wp = (const float*)(uintptr_t)cb.x;
        const float  cf = __uint_as_float((unsigned)cb.y);
        const bool act  = j < cnt;
        const bool lo   = j < cnt0;
        #pragma unroll
        for (int r = 0; r < RPW; ++r) {
            float wv = act ? __ldg(wp + (size_t)(row0 + r) * k + tap) : 0.f;
            float val = cf * wv;
            if (lo) acc0[r] += val; else acc1[r] += val;
        }
    }
    #undef UENT

    // 4) Edge tiles. pad -> flip -> roll((S+1)//2):
    //    out[t] = acc[28 - t]      t in [0, 29)
    //    out[t] = acc[N + 28 - t]  t in [N-28, N)
    //    Lane L holds acc[L] (acc0) and acc[L+32] (acc1).
    #pragma unroll
    for (int r = 0; r < RPW; ++r) {
        // Head tile: floats [0, 128)
        {
            const int t0 = lane * 4;
            float a[4];
            #pragma unroll
            for (int q = 0; q < 4; ++q) {
                const int idx = 28 - (t0 + q);
                const float g = __shfl_sync(0xffffffffu, acc0[r], idx & 31);
                a[q] = (idx >= 0) ? g : 0.f;
            }
            __stcs(&o[r][lane], make_float4(a[0], a[1], a[2], a[3]));
        }
        // Tail tile: floats [N-128, N); idx = N+28-t = 156 - 4*lane - q
        {
            float a[4];
            #pragma unroll
            for (int q = 0; q < 4; ++q) {
                const int idx = 156 - lane * 4 - q;   // >= 29 always
                const float glo = __shfl_sync(0xffffffffu, acc0[r], idx & 31);
                const float ghi = __shfl_sync(0xffffffffu, acc1[r], (idx - 32) & 31);
                const float g = (idx < 32) ? glo : ghi;
                a[q] = (idx <= 56) ? g : 0.f;
            }
            __stcs(&o[r][(nIt - 1) * 32 + lane], make_float4(a[0], a[1], a[2], a[3]));
        }
    }
}

extern "C" void kernel_launch(void* const* d_in, const int* in_sizes, int n_in,
                              void* d_out, int out_size) {
    const float* w[12];
    for (int i = 0; i < 12; ++i) w[i] = (const float*)d_in[i];
    const float* alpha   = (const float*)d_in[12];
    const float* gumbels = (const float*)d_in[13];
    float* out = (float*)d_out;

    const int rows = CO * CI;                 // 65536
    const int N = out_size / rows;            // input_size (1024)

    setup_kernel<<<1, 32>>>(alpha, gumbels,
                            w[0], w[1], w[2], w[3], w[4], w[5],
                            w[6], w[7], w[8], w[9], w[10], w[11]);
    mcp_kernel<<<rows / (8 * RPW), 256>>>(out, N);
}